// round 1
// baseline (speedup 1.0000x reference)
#include <cuda_runtime.h>
#include <cstdint>
#include <cstddef>

// Problem constants (fixed by the reference: B=8, N=4096, NITER=4)
constexpr int B = 8;
constexpr int N = 4096;
constexpr int NITER = 4;
constexpr int BN = B * N;

constexpr int NCHUNK = 64;         // b-dimension split
constexpr int CB = N / NCHUNK;     // 64 rows of P per chunk
constexpr int TILE_A = 512;        // output columns per block
constexpr int BLOCK_A = 128;       // threads per block (4 cols each)

// Static scratch (no allocations allowed)
__device__ float g_partial[(size_t)NCHUNK * BN];   // 8 MB partial products
__device__ float g_pred[BN];                       // current pred between iterations

using ull = unsigned long long;

__device__ __forceinline__ ull pk2(float x) {
    ull r; asm("mov.b64 %0, {%1, %1};" : "=l"(r) : "f"(x)); return r;
}
__device__ __forceinline__ ull fma2(ull a, ull b, ull c) {
    ull d; asm("fma.rn.f32x2 %0, %1, %2, %3;" : "=l"(d) : "l"(a), "l"(b), "l"(c)); return d;
}
__device__ __forceinline__ ull mul2(ull a, ull b) {
    ull d; asm("mul.rn.f32x2 %0, %1, %2;" : "=l"(d) : "l"(a), "l"(b)); return d;
}
__device__ __forceinline__ void upk2(ull v, float& lo, float& hi) {
    asm("mov.b64 {%0, %1}, %2;" : "=f"(lo), "=f"(hi) : "l"(v));
}

constexpr ull ONE2 = 0x3F8000003F800000ULL;  // (1.0f, 1.0f)

// Kernel A: partial products.
// Block (ax, c): output columns a in [ax*512, ax*512+512), P rows b in [c*64, c*64+64).
// Each thread: 4 consecutive a columns x 8 batches (4 f32x2 accumulators per a).
__global__ void __launch_bounds__(BLOCK_A) propA(const float* __restrict__ P,
                                                 const float* __restrict__ pred_ext,
                                                 int use_ext) {
    __shared__ ull s_np[CB * 4];                   // negated pred, batch-paired
    float* s_f = reinterpret_cast<float*>(s_np);   // s_f[b*8 + i] = -pred[i][b0+b]

    const int tid = threadIdx.x;
    const int c = blockIdx.y;
    const int b0 = c * CB;
    const float* __restrict__ pred = use_ext ? pred_ext : g_pred;

#pragma unroll
    for (int j = 0; j < (CB * B) / BLOCK_A; j++) {
        int idx = j * BLOCK_A + tid;
        int i = idx >> 6;          // batch 0..7
        int b = idx & (CB - 1);    // local row
        s_f[b * 8 + i] = -pred[i * N + b0 + b];
    }
    __syncthreads();

    const int a0 = blockIdx.x * TILE_A + tid * 4;
    const float4* __restrict__ p4 =
        reinterpret_cast<const float4*>(P + (size_t)b0 * N) + (a0 >> 2);

    ull acc[4][4];
#pragma unroll
    for (int ai = 0; ai < 4; ai++)
#pragma unroll
        for (int p = 0; p < 4; p++) acc[ai][p] = ONE2;

#pragma unroll 4
    for (int b = 0; b < CB; b++) {
        float4 pv = __ldg(&p4[b * (N >> 2)]);
        ull P2[4] = { pk2(pv.x), pk2(pv.y), pk2(pv.z), pk2(pv.w) };
        ull np[4];
#pragma unroll
        for (int p = 0; p < 4; p++) np[p] = s_np[b * 4 + p];
#pragma unroll
        for (int ai = 0; ai < 4; ai++)
#pragma unroll
            for (int p = 0; p < 4; p++)
                acc[ai][p] = mul2(acc[ai][p], fma2(P2[ai], np[p], ONE2));
    }

    float* outc = g_partial + (size_t)c * BN;
#pragma unroll
    for (int p = 0; p < 4; p++) {
        float lo[4], hi[4];
#pragma unroll
        for (int ai = 0; ai < 4; ai++) upk2(acc[ai][p], lo[ai], hi[ai]);
        *reinterpret_cast<float4*>(outc + (size_t)(2 * p) * N + a0) =
            make_float4(lo[0], lo[1], lo[2], lo[3]);
        *reinterpret_cast<float4*>(outc + (size_t)(2 * p + 1) * N + a0) =
            make_float4(hi[0], hi[1], hi[2], hi[3]);
    }
}

// Kernel B: combine chunk partials, seed clamp, write next pred (+ optionally d_out).
__global__ void __launch_bounds__(256) propC(const int2* __restrict__ seed, int nseeds,
                                             float* __restrict__ final_out) {
    __shared__ int s_flat[128];
    const int tid = threadIdx.x;
    if (tid < nseeds) {
        int2 s = seed[tid];
        s_flat[tid] = s.x * N + s.y;
    }
    __syncthreads();

    const int idx = blockIdx.x * 256 + tid;
    float p0 = 1.f, p1 = 1.f, p2 = 1.f, p3 = 1.f;
#pragma unroll
    for (int c = 0; c < NCHUNK; c += 4) {
        p0 *= g_partial[(size_t)(c + 0) * BN + idx];
        p1 *= g_partial[(size_t)(c + 1) * BN + idx];
        p2 *= g_partial[(size_t)(c + 2) * BN + idx];
        p3 *= g_partial[(size_t)(c + 3) * BN + idx];
    }
    float v = 1.0f - (p0 * p1) * (p2 * p3);
    for (int s = 0; s < nseeds; s++)
        if (s_flat[s] == idx) v = 1.0f;
    g_pred[idx] = v;
    if (final_out) final_out[idx] = v;
}

extern "C" void kernel_launch(void* const* d_in, const int* in_sizes, int n_in,
                              void* d_out, int out_size) {
    const float* preds = (const float*)d_in[0];      // [B, N] fp32
    const float* P = (const float*)d_in[1];          // [N, N] fp32, P[b*N + a]
    const int2* seed = (const int2*)d_in[2];         // [NSEEDS, 2] int32 (b, n)
    int nseeds = in_sizes[2] / 2;
    if (nseeds > 128) nseeds = 128;
    float* out = (float*)d_out;

    dim3 gridA(N / TILE_A, NCHUNK);   // (8, 64) = 512 blocks
    dim3 gridC(BN / 256);             // 128 blocks

    for (int t = 0; t < NITER; t++) {
        propA<<<gridA, BLOCK_A>>>(P, preds, t == 0 ? 1 : 0);
        propC<<<gridC, 256>>>(seed, nseeds, (t == NITER - 1) ? out : nullptr);
    }
}

// round 3
// speedup vs baseline: 1.0299x; 1.0299x over previous
#include <cuda_runtime.h>
#include <cstdint>
#include <cstddef>

// Problem constants (fixed by the reference: B=8, N=4096, NITER=4)
constexpr int B = 8;
constexpr int N = 4096;
constexpr int NITER = 4;
constexpr int BN = B * N;

constexpr int NCHUNK = 64;         // b-dimension split
constexpr int CB = N / NCHUNK;     // 64 rows of P per chunk
constexpr int TILE_A = 256;        // output columns per block
constexpr int BLOCK_A = 64;        // threads per block (4 cols each)

// Static scratch (no allocations allowed)
__device__ float g_partial[(size_t)NCHUNK * BN];   // 8 MB partial products
__device__ float g_pred[BN];                       // current pred between iterations

using ull = unsigned long long;

__device__ __forceinline__ ull pk2(float x) {
    ull r; asm("mov.b64 %0, {%1, %1};" : "=l"(r) : "f"(x)); return r;
}
__device__ __forceinline__ ull fma2(ull a, ull b, ull c) {
    ull d; asm("fma.rn.f32x2 %0, %1, %2, %3;" : "=l"(d) : "l"(a), "l"(b), "l"(c)); return d;
}
__device__ __forceinline__ ull mul2(ull a, ull b) {
    ull d; asm("mul.rn.f32x2 %0, %1, %2;" : "=l"(d) : "l"(a), "l"(b)); return d;
}
__device__ __forceinline__ void upk2(ull v, float& lo, float& hi) {
    asm("mov.b64 {%0, %1}, %2;" : "=f"(lo), "=f"(hi) : "l"(v));
}

constexpr ull ONE2 = 0x3F8000003F800000ULL;  // (1.0f, 1.0f)

// Kernel A: partial products.
// Block (ax, c): output columns a in [ax*256, ax*256+256), P rows b in [c*64, c*64+64).
// Each thread: 4 consecutive a columns x 8 batches (4 f32x2 accumulators per a).
// Grid = (16, 64) = 1024 blocks of 64 threads -> ~6.9 blocks/SM, small tail.
__global__ void __launch_bounds__(BLOCK_A) propA(const float* __restrict__ P,
                                                 const float* __restrict__ pred_ext,
                                                 int use_ext) {
    __shared__ ull s_np[CB * 4];                   // negated pred, batch-paired (2KB)
    float* s_f = reinterpret_cast<float*>(s_np);   // s_f[b*8 + i] = -pred[i][b0+b]

    const int tid = threadIdx.x;
    const int c = blockIdx.y;
    const int b0 = c * CB;
    const float* __restrict__ pred = use_ext ? pred_ext : g_pred;

#pragma unroll
    for (int j = 0; j < (CB * B) / BLOCK_A; j++) {
        int idx = j * BLOCK_A + tid;
        int i = idx >> 6;          // batch 0..7
        int b = idx & (CB - 1);    // local row
        s_f[b * 8 + i] = -pred[i * N + b0 + b];
    }
    __syncthreads();

    const int a0 = blockIdx.x * TILE_A + tid * 4;
    const float4* __restrict__ p4 =
        reinterpret_cast<const float4*>(P + (size_t)b0 * N) + (a0 >> 2);

    ull acc[4][4];
#pragma unroll
    for (int ai = 0; ai < 4; ai++)
#pragma unroll
        for (int p = 0; p < 4; p++) acc[ai][p] = ONE2;

#pragma unroll 4
    for (int b = 0; b < CB; b++) {
        float4 pv = __ldg(&p4[b * (N >> 2)]);
        ull P2[4] = { pk2(pv.x), pk2(pv.y), pk2(pv.z), pk2(pv.w) };
        ull np[4];
#pragma unroll
        for (int p = 0; p < 4; p++) np[p] = s_np[b * 4 + p];
#pragma unroll
        for (int ai = 0; ai < 4; ai++)
#pragma unroll
            for (int p = 0; p < 4; p++)
                acc[ai][p] = mul2(acc[ai][p], fma2(P2[ai], np[p], ONE2));
    }

    float* outc = g_partial + (size_t)c * BN;
#pragma unroll
    for (int p = 0; p < 4; p++) {
        float lo[4], hi[4];
#pragma unroll
        for (int ai = 0; ai < 4; ai++) upk2(acc[ai][p], lo[ai], hi[ai]);
        *reinterpret_cast<float4*>(outc + (size_t)(2 * p) * N + a0) =
            make_float4(lo[0], lo[1], lo[2], lo[3]);
        *reinterpret_cast<float4*>(outc + (size_t)(2 * p + 1) * N + a0) =
            make_float4(hi[0], hi[1], hi[2], hi[3]);
    }
}

// Kernel C: combine chunk partials, seed clamp, write next pred (+ optionally d_out).
// 4 threads cooperate on one output quad (4 consecutive flat indices); each thread
// reads 16 float4 planes (fully coalesced, MLP=16), then butterfly-shfl combine.
// Grid = BN/128 = 256 blocks of 128 threads.
__global__ void __launch_bounds__(128) propC(const int2* __restrict__ seed, int nseeds,
                                             float* __restrict__ final_out) {
    __shared__ int s_flat[128];
    const int tid = threadIdx.x;
    if (tid < nseeds) {
        int2 s = seed[tid];
        s_flat[tid] = s.x * N + s.y;
    }
    __syncthreads();

    const int g = blockIdx.x * 128 + tid;
    const int q = g >> 2;          // output quad id
    const int sub = g & 3;         // which 16-plane group this thread reduces

    const float4* __restrict__ base = reinterpret_cast<const float4*>(g_partial) + q;
    constexpr int PLANE4 = BN / 4;  // float4 stride between planes

    float4 a0 = make_float4(1.f, 1.f, 1.f, 1.f);
    float4 a1 = make_float4(1.f, 1.f, 1.f, 1.f);
#pragma unroll
    for (int k = 0; k < 16; k += 2) {
        float4 v = __ldg(&base[(size_t)(sub * 16 + k) * PLANE4]);
        float4 w = __ldg(&base[(size_t)(sub * 16 + k + 1) * PLANE4]);
        a0.x *= v.x; a0.y *= v.y; a0.z *= v.z; a0.w *= v.w;
        a1.x *= w.x; a1.y *= w.y; a1.z *= w.z; a1.w *= w.w;
    }
    a0.x *= a1.x; a0.y *= a1.y; a0.z *= a1.z; a0.w *= a1.w;

    // butterfly across the 4 subs (lanes of the same quad sit in one warp)
#pragma unroll
    for (int m = 1; m < 4; m <<= 1) {
        a0.x *= __shfl_xor_sync(0xffffffffu, a0.x, m);
        a0.y *= __shfl_xor_sync(0xffffffffu, a0.y, m);
        a0.z *= __shfl_xor_sync(0xffffffffu, a0.z, m);
        a0.w *= __shfl_xor_sync(0xffffffffu, a0.w, m);
    }

    float prod = (sub == 0) ? a0.x : (sub == 1) ? a0.y : (sub == 2) ? a0.z : a0.w;
    float v = 1.0f - prod;
    for (int s = 0; s < nseeds; s++)
        if (s_flat[s] == g) v = 1.0f;
    g_pred[g] = v;
    if (final_out) final_out[g] = v;
}

extern "C" void kernel_launch(void* const* d_in, const int* in_sizes, int n_in,
                              void* d_out, int out_size) {
    const float* preds = (const float*)d_in[0];      // [B, N] fp32
    const float* P = (const float*)d_in[1];          // [N, N] fp32, P[b*N + a]
    const int2* seed = (const int2*)d_in[2];         // [NSEEDS, 2] int32 (b, n)
    int nseeds = in_sizes[2] / 2;
    if (nseeds > 128) nseeds = 128;
    float* out = (float*)d_out;

    dim3 gridA(N / TILE_A, NCHUNK);   // (16, 64) = 1024 blocks
    dim3 gridC(BN / 128);             // 256 blocks

    for (int t = 0; t < NITER; t++) {
        propA<<<gridA, BLOCK_A>>>(P, preds, t == 0 ? 1 : 0);
        propC<<<gridC, 128>>>(seed, nseeds, (t == NITER - 1) ? out : nullptr);
    }
}